// round 5
// baseline (speedup 1.0000x reference)
#include <cuda_runtime.h>
#include <cuda_fp16.h>
#include <cuda_bf16.h>

#define NMAX 100000
#define EMAX 1700000
#define D 64

// Scratch (allocation-free: __device__ globals). Index [graph] via offsets.
// INVARIANT: g_deg and g_sums are zero at entry to kernel_launch (zero-init at
// module load; re-zeroed at the end of fc_k every call).
__device__ __half g_h[2 * NMAX * D];    // matmul output / gather source (fp16)
__device__ float  g_y[2 * NMAX * D];    // layer output (post relu, fp32)
__device__ int    g_deg[2 * NMAX];
__device__ float  g_dinv[2 * NMAX];
__device__ int    g_rowptr[2 * (NMAX + 1)];
__device__ int    g_fill[2 * NMAX];     // moving fill pointer for CSR build
__device__ int    g_col[2 * EMAX];
__device__ int    g_bsum[2 * 128];
__device__ float  g_sums[2 * D];

// ---------------------------------------------------------------------------
__global__ void degree_k(const int* __restrict__ e1, const int* __restrict__ e2,
                         int E1, int E2) {
    int g = blockIdx.y;
    int E = g ? E2 : E1;
    const int* dst = (g ? e2 : e1) + E;   // second half of edge_index = dst
    int i = blockIdx.x * blockDim.x + threadIdx.x;
    if (i < E) atomicAdd(&g_deg[g * NMAX + dst[i]], 1);
}

// ---- exclusive prefix scan of g_deg -> g_rowptr (block-local) -------------
__global__ void scan_block_k(int n) {
    __shared__ int s[1024];
    int g = blockIdx.y;
    int gid = blockIdx.x * 1024 + threadIdx.x;
    int v = (gid < n) ? g_deg[g * NMAX + gid] : 0;
    s[threadIdx.x] = v;
    __syncthreads();
#pragma unroll
    for (int off = 1; off < 1024; off <<= 1) {
        int t = 0;
        if (threadIdx.x >= off) t = s[threadIdx.x - off];
        __syncthreads();
        if (threadIdx.x >= off) s[threadIdx.x] += t;
        __syncthreads();
    }
    if (gid < n) g_rowptr[g * (NMAX + 1) + gid] = s[threadIdx.x] - v;  // exclusive
    if (threadIdx.x == 1023) g_bsum[g * 128 + blockIdx.x] = s[1023];
}

// rowptr += prefix(block sums); init fill ptr; dinv = rsqrt(deg+1)
__global__ void finalize_csr_k(int n, int E1, int E2, int nb) {
    int g = blockIdx.y;
    int gid = blockIdx.x * blockDim.x + threadIdx.x;
    int bucket = gid >> 10;
    int off = 0;
    const int* bs = g_bsum + g * 128;
    for (int i = 0; i < nb; i++)          // broadcast loads; bucket uniform in warp
        if (i < bucket) off += __ldg(&bs[i]);
    if (gid < n) {
        int rp = g_rowptr[g * (NMAX + 1) + gid] + off;
        g_rowptr[g * (NMAX + 1) + gid] = rp;
        g_fill[g * NMAX + gid] = rp;
        g_dinv[g * NMAX + gid] = rsqrtf((float)g_deg[g * NMAX + gid] + 1.0f);
    }
    if (gid == n) g_rowptr[g * (NMAX + 1) + n] = g ? E2 : E1;
}

__global__ void fill_k(const int* __restrict__ e1, const int* __restrict__ e2,
                       int E1, int E2) {
    int g = blockIdx.y;
    int E = g ? E2 : E1;
    const int* ei = g ? e2 : e1;
    int e = blockIdx.x * blockDim.x + threadIdx.x;
    if (e >= E) return;
    int s = ei[e];         // src
    int d = ei[E + e];     // dst
    int slot = atomicAdd(&g_fill[g * NMAX + d], 1);
    g_col[g * EMAX + slot] = s;
}

// ---------------------------------------------------------------------------
// h = in @ W (fp16 out).  W[:,j] in 64 regs per thread; x row via broadcast LDG.
#define RPB 64
__global__ void matmul_k(const float* __restrict__ x1, const float* __restrict__ x2,
                         const float* __restrict__ W, int use_y, int n) {
    int g = blockIdx.y;
    int j = threadIdx.x & 63;
    int rg = threadIdx.x >> 6;  // 0..3
    const float* xin = use_y ? (g_y + (size_t)g * NMAX * D) : (g ? x2 : x1);
    __half* hout = g_h + (size_t)g * NMAX * D;

    float w[64];
#pragma unroll
    for (int k = 0; k < 64; k++) w[k] = W[k * 64 + j];  // coalesced over j

    int rend = min((blockIdx.x + 1) * RPB, n);
    for (int r = blockIdx.x * RPB + rg; r < rend; r += 4) {
        const float4* xv = reinterpret_cast<const float4*>(xin + (size_t)r * D);
        float a0 = 0.f, a1 = 0.f, a2 = 0.f, a3 = 0.f;  // 4 chains for ILP
#pragma unroll
        for (int k4 = 0; k4 < 16; k4 += 4) {
            float4 t0 = xv[k4 + 0], t1 = xv[k4 + 1], t2 = xv[k4 + 2], t3 = xv[k4 + 3];
            a0 += t0.x * w[4*k4+0]  + t0.y * w[4*k4+1]  + t0.z * w[4*k4+2]  + t0.w * w[4*k4+3];
            a1 += t1.x * w[4*k4+4]  + t1.y * w[4*k4+5]  + t1.z * w[4*k4+6]  + t1.w * w[4*k4+7];
            a2 += t2.x * w[4*k4+8]  + t2.y * w[4*k4+9]  + t2.z * w[4*k4+10] + t2.w * w[4*k4+11];
            a3 += t3.x * w[4*k4+12] + t3.y * w[4*k4+13] + t3.z * w[4*k4+14] + t3.w * w[4*k4+15];
        }
        hout[(size_t)r * D + j] = __float2half_rn((a0 + a1) + (a2 + a3));
    }
}

// ---------------------------------------------------------------------------
// Warp-per-row aggregation: lane l owns half2 element l of the 64-wide row.
// y[d] = relu(b + dinv[d]^2*h[d] + sum_nb dinv[s]*dinv[d]*h[s])
// Grid-stride over rows; pool sums accumulate in registers per lane.
__global__ void aggregate_k(const float* __restrict__ b, int n, int do_pool) {
    int g = blockIdx.y;
    int lane = threadIdx.x & 31;
    int wid = threadIdx.x >> 5;
    int wpb = blockDim.x >> 5;
    int warp = blockIdx.x * wpb + wid;
    int nwarps = gridDim.x * wpb;

    const __half2* hv = reinterpret_cast<const __half2*>(g_h + (size_t)g * NMAX * D);
    float2* yv = reinterpret_cast<float2*>(g_y + (size_t)g * NMAX * D);
    const float* dinv = g_dinv + g * NMAX;
    const int* col = g_col + (size_t)g * EMAX;
    const int* rowptr = g_rowptr + g * (NMAX + 1);

    float2 bb = reinterpret_cast<const float2*>(b)[lane];
    float px = 0.f, py = 0.f;

    for (int row = warp; row < n; row += nwarps) {
        float dd = dinv[row];
        float2 hs = __half22float2(hv[row * 32 + lane]);
        float ns = dd * dd;
        float ax = hs.x * ns, ay = hs.y * ns;

        int p0 = rowptr[row];
        int p1 = rowptr[row + 1];
        int p = p0;
        for (; p + 4 <= p1; p += 4) {
            int i0 = col[p + 0], i1 = col[p + 1], i2 = col[p + 2], i3 = col[p + 3];
            float n0 = dd * dinv[i0], n1 = dd * dinv[i1];
            float n2 = dd * dinv[i2], n3 = dd * dinv[i3];
            float2 v0 = __half22float2(hv[i0 * 32 + lane]);
            float2 v1 = __half22float2(hv[i1 * 32 + lane]);
            float2 v2 = __half22float2(hv[i2 * 32 + lane]);
            float2 v3 = __half22float2(hv[i3 * 32 + lane]);
            ax += v0.x * n0; ay += v0.y * n0;
            ax += v1.x * n1; ay += v1.y * n1;
            ax += v2.x * n2; ay += v2.y * n2;
            ax += v3.x * n3; ay += v3.y * n3;
        }
        for (; p < p1; p++) {
            int i0 = col[p];
            float n0 = dd * dinv[i0];
            float2 v0 = __half22float2(hv[i0 * 32 + lane]);
            ax += v0.x * n0; ay += v0.y * n0;
        }

        float yx = fmaxf(ax + bb.x, 0.f);
        float yy = fmaxf(ay + bb.y, 0.f);
        yv[row * 32 + lane] = make_float2(yx, yy);
        px += yx; py += yy;
    }

    if (do_pool) {
        __shared__ float s[64];
        if (threadIdx.x < 64) s[threadIdx.x] = 0.0f;
        __syncthreads();
        atomicAdd(&s[2 * lane + 0], px);
        atomicAdd(&s[2 * lane + 1], py);
        __syncthreads();
        if (threadIdx.x < 64) atomicAdd(&g_sums[g * 64 + threadIdx.x], s[threadIdx.x]);
    }
}

// out[g][j] = fc_b[j] + sum_k mean[g][k] * fc_w[j,k]
// Also restores the zero-invariant on g_deg / g_sums for the next replay.
__global__ void fc_k(const float* __restrict__ fcw, const float* __restrict__ fcb,
                     float* __restrict__ out, float invn, int n) {
    if (blockIdx.x == 0 && threadIdx.x < 128) {
        int g = threadIdx.x >> 6;
        int j = threadIdx.x & 63;
        float m[D];
#pragma unroll
        for (int k = 0; k < D; k++) m[k] = g_sums[g * 64 + k];
        float acc = fcb[j];
#pragma unroll 16
        for (int k = 0; k < D; k++)
            acc += (m[k] * invn) * fcw[j * D + k];
        out[g * 64 + j] = acc;
    }
    __syncthreads();  // block 0: all sums reads done before zeroing below
    // zero g_deg (grid-stride) and g_sums (block 0) for the next call
    for (int i = blockIdx.x * blockDim.x + threadIdx.x; i < 2 * n;
         i += gridDim.x * blockDim.x)
        g_deg[i] = 0;
    if (blockIdx.x == 0 && threadIdx.x < 2 * D) g_sums[threadIdx.x] = 0.0f;
}

// ---------------------------------------------------------------------------
extern "C" void kernel_launch(void* const* d_in, const int* in_sizes, int n_in,
                              void* d_out, int out_size) {
    const float* x1  = (const float*)d_in[0];
    const float* x2  = (const float*)d_in[1];
    const int*   e1  = (const int*)d_in[2];
    const int*   e2  = (const int*)d_in[3];
    const float* W1  = (const float*)d_in[4];
    const float* b1  = (const float*)d_in[5];
    const float* W2  = (const float*)d_in[6];
    const float* b2  = (const float*)d_in[7];
    const float* fcw = (const float*)d_in[8];
    const float* fcb = (const float*)d_in[9];

    int n  = in_sizes[0] / D;
    int E1 = in_sizes[2] / 2;
    int E2 = in_sizes[3] / 2;
    int Emax = max(E1, E2);
    float* out = (float*)d_out;

    const int T = 256;
    int nb = (n + 1023) / 1024;
    dim3 eBlk((Emax + T - 1) / T, 2);
    dim3 scanBlk(nb, 2);
    dim3 finBlk((n + T) / T, 2);
    dim3 mmBlk((n + RPB - 1) / RPB, 2);
    dim3 aggBlk(1184, 2);

    // CSR build (once; reused by both layers). g_deg is pre-zeroed (invariant).
    degree_k<<<eBlk, T>>>(e1, e2, E1, E2);              // 1
    scan_block_k<<<scanBlk, 1024>>>(n);                 // 2
    finalize_csr_k<<<finBlk, T>>>(n, E1, E2, nb);       // 3
    fill_k<<<eBlk, T>>>(e1, e2, E1, E2);                // 4  <- profiled slot

    // layer 1
    matmul_k<<<mmBlk, T>>>(x1, x2, W1, 0, n);           // 5
    aggregate_k<<<aggBlk, T>>>(b1, n, 0);               // 6

    // layer 2 (input = g_y); aggregation also does the mean-pool reduction
    matmul_k<<<mmBlk, T>>>(x1, x2, W2, 1, n);           // 7
    aggregate_k<<<aggBlk, T>>>(b2, n, 1);               // 8

    fc_k<<<782, T>>>(fcw, fcb, out, 1.0f / (float)n, n); // 9 (+ re-zero)
}